// round 5
// baseline (speedup 1.0000x reference)
#include <cuda_runtime.h>

// Problem constants (fixed by the reference setup)
#define S_DIM   4
#define B_DIM   2
#define F_DIM   64
#define P_DIM   16
#define KTOT    80          // F_DIM + P_DIM
#define HID     32
#define NPIX    131072      // T*H*W = 32*64*64, per (s,b) slice
#define BN_EPS  1e-5f

#define TPB     128         // threads per block
#define PX_BLK  256         // pixels per block (2 px / thread)

// ---------------------------------------------------------------------------
// Packed fp32x2 helpers (packed fp32 pipe)
// ---------------------------------------------------------------------------
__device__ __forceinline__ unsigned long long pack2(float a, float b) {
    unsigned long long r;
    asm("mov.b64 %0, {%1, %2};" : "=l"(r) : "f"(a), "f"(b));
    return r;
}
__device__ __forceinline__ void unpack2(unsigned long long v, float& a, float& b) {
    asm("mov.b64 {%0, %1}, %2;" : "=f"(a), "=f"(b) : "l"(v));
}
__device__ __forceinline__ unsigned long long fma2(unsigned long long a,
                                                   unsigned long long b,
                                                   unsigned long long c) {
    unsigned long long r;
    asm("fma.rn.f32x2 %0, %1, %2, %3;" : "=l"(r) : "l"(a), "l"(b), "l"(c));
    return r;
}

// ---------------------------------------------------------------------------
// Single fused kernel, h-only register state (p contribution recomputed per s;
// +18% FMA but frees 64 regs -> no spills, 3 CTAs/SM).
// Weights in smem as [k][o], read via LDS.128 broadcast (8 loads per k-step).
// ---------------------------------------------------------------------------
__global__ __launch_bounds__(TPB, 3)
void gssm_kernel(const float* __restrict__ feats,
                 const float* __restrict__ p_s,
                 const float* __restrict__ w1,
                 const float* __restrict__ gamma,
                 const float* __restrict__ beta,
                 const float* __restrict__ mean,
                 const float* __restrict__ var,
                 const float* __restrict__ w2v,
                 float* __restrict__ out) {
    __shared__ __align__(16) float s_wT[KTOT][HID];   // 10 KB, wT[k][o]
    __shared__ float s_bias[HID];
    __shared__ float s_w2[HID];
    __shared__ float s_scale[HID];

    const int t = threadIdx.x;

    // ---- prologue: BN-folded weights into smem (bit-op indexing only) ----
    if (t < HID) {
        float sc = gamma[t] * rsqrtf(var[t] + BN_EPS);
        s_scale[t] = sc;
        s_bias[t]  = beta[t] - mean[t] * sc;
        s_w2[t]    = w2v[t];
    }
    __syncthreads();
#pragma unroll
    for (int i = t; i < HID * KTOT; i += TPB) {
        int o = i & (HID - 1);          // i % 32
        int k = i >> 5;                 // i / 32
        s_wT[k][o] = w1[o * KTOT + k] * s_scale[o];
    }
    __syncthreads();

    // ---- pixel pair for this thread ----
    long n0 = (long)blockIdx.x * PX_BLK + t * 2;
    int  b  = (int)(n0 / NPIX);
    int  m  = (int)(n0 % NPIX);

    const float* pbase = p_s + (long)b * P_DIM * NPIX + m;

    // ---- per-s: h = Wf*x + Wp*p, relu(h+bias), logit = w2.h ----
    float logits[S_DIM][2];
#pragma unroll 1
    for (int s = 0; s < S_DIM; s++) {
        unsigned long long h[HID / 2][2];
#pragma unroll
        for (int op = 0; op < HID / 2; op++) { h[op][0] = 0ull; h[op][1] = 0ull; }

        const float* fb = feats + ((long)(s * B_DIM + b) * F_DIM) * NPIX + m;
#pragma unroll 4
        for (int f = 0; f < F_DIM; f++) {
            float2 x = *(const float2*)(fb + (long)f * NPIX);
            unsigned long long x0 = pack2(x.x, x.x);
            unsigned long long x1 = pack2(x.y, x.y);
#pragma unroll
            for (int q = 0; q < 8; q++) {
                ulonglong2 w = *(const ulonglong2*)&s_wT[f][4 * q];   // LDS.128 bcast
                h[2 * q][0]     = fma2(w.x, x0, h[2 * q][0]);
                h[2 * q][1]     = fma2(w.x, x1, h[2 * q][1]);
                h[2 * q + 1][0] = fma2(w.y, x0, h[2 * q + 1][0]);
                h[2 * q + 1][1] = fma2(w.y, x1, h[2 * q + 1][1]);
            }
        }
        // p contribution (recomputed per s; L1-hot after s=0)
#pragma unroll 4
        for (int p = 0; p < P_DIM; p++) {
            float2 x = *(const float2*)(pbase + (long)p * NPIX);
            unsigned long long x0 = pack2(x.x, x.x);
            unsigned long long x1 = pack2(x.y, x.y);
#pragma unroll
            for (int q = 0; q < 8; q++) {
                ulonglong2 w = *(const ulonglong2*)&s_wT[F_DIM + p][4 * q];
                h[2 * q][0]     = fma2(w.x, x0, h[2 * q][0]);
                h[2 * q][1]     = fma2(w.x, x1, h[2 * q][1]);
                h[2 * q + 1][0] = fma2(w.y, x0, h[2 * q + 1][0]);
                h[2 * q + 1][1] = fma2(w.y, x1, h[2 * q + 1][1]);
            }
        }

        float l0 = 0.f, l1 = 0.f;
#pragma unroll
        for (int op = 0; op < HID / 2; op++) {
            float b0 = s_bias[2 * op], b1 = s_bias[2 * op + 1];
            float w20 = s_w2[2 * op],  w21 = s_w2[2 * op + 1];
            float a, c;
            unpack2(h[op][0], a, c);
            l0 += fmaxf(a + b0, 0.f) * w20 + fmaxf(c + b1, 0.f) * w21;
            unpack2(h[op][1], a, c);
            l1 += fmaxf(a + b0, 0.f) * w20 + fmaxf(c + b1, 0.f) * w21;
        }
        logits[s][0] = l0;
        logits[s][1] = l1;
    }

    // ---- softmax over s (b2 constant shift cancels) ----
    float alpha[S_DIM][2];
#pragma unroll
    for (int px = 0; px < 2; px++) {
        float mx = fmaxf(fmaxf(logits[0][px], logits[1][px]),
                         fmaxf(logits[2][px], logits[3][px]));
        float sum = 0.f;
#pragma unroll
        for (int s = 0; s < S_DIM; s++) {
            float e = __expf(logits[s][px] - mx);
            alpha[s][px] = e;
            sum += e;
        }
        float inv = 1.f / sum;
#pragma unroll
        for (int s = 0; s < S_DIM; s++) alpha[s][px] *= inv;
    }

    // ---- write alpha: layout (B, S, NPIX), after the out region ----
    float* aout = out + (long)B_DIM * F_DIM * NPIX;
#pragma unroll
    for (int s = 0; s < S_DIM; s++) {
        *(float2*)(aout + ((long)b * S_DIM + s) * NPIX + m) =
            make_float2(alpha[s][0], alpha[s][1]);
    }

    // ---- pass 2: out[b,f] = sum_s alpha_s * feats[s,b,f] ----
    const float* fb0 = feats + ((long)b * F_DIM) * NPIX + m;   // s = 0
    const long   sstride = (long)B_DIM * F_DIM * NPIX;
#pragma unroll 8
    for (int f = 0; f < F_DIM; f++) {
        float2 acc = make_float2(0.f, 0.f);
#pragma unroll
        for (int s = 0; s < S_DIM; s++) {
            float2 x = *(const float2*)(fb0 + s * sstride + (long)f * NPIX);
            acc.x = fmaf(x.x, alpha[s][0], acc.x);
            acc.y = fmaf(x.y, alpha[s][1], acc.y);
        }
        *(float2*)(out + ((long)b * F_DIM + f) * NPIX + m) = acc;
    }
}

// ---------------------------------------------------------------------------
// Launch: inputs in metadata order:
//   0 feats, 1 p_s, 2 w1, 3 bn_gamma, 4 bn_beta, 5 bn_mean, 6 bn_var, 7 w2, 8 b2
// d_out = [out (B*F*NPIX floats)] ++ [alpha (B*S*NPIX floats)]
// ---------------------------------------------------------------------------
extern "C" void kernel_launch(void* const* d_in, const int* in_sizes, int n_in,
                              void* d_out, int out_size) {
    const float* feats = (const float*)d_in[0];
    const float* p_s   = (const float*)d_in[1];
    const float* w1    = (const float*)d_in[2];
    const float* gam   = (const float*)d_in[3];
    const float* bet   = (const float*)d_in[4];
    const float* mean  = (const float*)d_in[5];
    const float* var   = (const float*)d_in[6];
    const float* w2    = (const float*)d_in[7];
    float* outp = (float*)d_out;

    const long total_px = (long)B_DIM * NPIX;          // 262144
    int blocks = (int)(total_px / PX_BLK);             // 1024 blocks
    gssm_kernel<<<blocks, TPB>>>(feats, p_s, w1, gam, bet, mean, var, w2, outp);
}

// round 6
// speedup vs baseline: 2.4034x; 2.4034x over previous
#include <cuda_runtime.h>

// Problem constants (fixed by the reference setup)
#define S_DIM   4
#define B_DIM   2
#define F_DIM   64
#define P_DIM   16
#define KTOT    80          // F_DIM + P_DIM
#define HID     32
#define NPIX    131072      // T*H*W = 32*64*64, per (s,b) slice
#define BN_EPS  1e-5f

#define TPB     256         // threads per block
#define PX_BLK  256         // pixels per block (thread pair = 2 px, 16 o each)

// ---------------------------------------------------------------------------
// Packed fp32x2 helpers
// ---------------------------------------------------------------------------
__device__ __forceinline__ unsigned long long pack2(float a, float b) {
    unsigned long long r;
    asm("mov.b64 %0, {%1, %2};" : "=l"(r) : "f"(a), "f"(b));
    return r;
}
__device__ __forceinline__ void unpack2(unsigned long long v, float& a, float& b) {
    asm("mov.b64 {%0, %1}, %2;" : "=f"(a), "=f"(b) : "l"(v));
}
__device__ __forceinline__ unsigned long long fma2(unsigned long long a,
                                                   unsigned long long b,
                                                   unsigned long long c) {
    unsigned long long r;
    asm("fma.rn.f32x2 %0, %1, %2, %3;" : "=l"(r) : "l"(a), "l"(b), "l"(c));
    return r;
}

// ---------------------------------------------------------------------------
// o-split fused kernel:
//   thread pair (2k, 2k+1) shares 2 pixels; thread handles 16 of 32 hidden o.
//   h state = 16 f32x2 regs. Partial logits combined via shfl_xor(1).
//   Pass 2: each thread of the pair does 1 pixel x 64 f (coalesced scalars).
// ---------------------------------------------------------------------------
__global__ __launch_bounds__(TPB, 2)
void gssm_kernel(const float* __restrict__ feats,
                 const float* __restrict__ p_s,
                 const float* __restrict__ w1,
                 const float* __restrict__ gamma,
                 const float* __restrict__ beta,
                 const float* __restrict__ mean,
                 const float* __restrict__ var,
                 const float* __restrict__ w2v,
                 float* __restrict__ out) {
    __shared__ __align__(16) float s_wT[KTOT][HID];   // 10 KB, wT[k][o] BN-folded
    __shared__ float s_bias[HID];
    __shared__ float s_w2[HID];
    __shared__ float s_scale[HID];

    const int t = threadIdx.x;

    // ---- prologue: BN-folded weights into smem ----
    if (t < HID) {
        float sc = gamma[t] * rsqrtf(var[t] + BN_EPS);
        s_scale[t] = sc;
        s_bias[t]  = beta[t] - mean[t] * sc;
        s_w2[t]    = w2v[t];
    }
    __syncthreads();
#pragma unroll 2
    for (int i = t; i < HID * KTOT; i += TPB) {
        int o = i & (HID - 1);          // i % 32
        int k = i >> 5;                 // i / 32
        s_wT[k][o] = w1[o * KTOT + k] * s_scale[o];
    }
    __syncthreads();

    // ---- pixel pair shared by thread pair; o-half per thread ----
    const int oh = t & 1;               // 0 or 1: which 16 o's
    const int wo = oh << 4;             // o base: 0 or 16
    long n0 = (long)blockIdx.x * PX_BLK + (t >> 1) * 2;
    int  b  = (int)(n0 / NPIX);
    int  m  = (int)(n0 % NPIX);

    const float* pbase = p_s + (long)b * P_DIM * NPIX + m;

    // ---- per-s: h = Wf*x + Wp*p (16 o's), relu, partial logit, shfl-combine
    float logits[S_DIM][2];
#pragma unroll 1
    for (int s = 0; s < S_DIM; s++) {
        unsigned long long h[8][2];     // 8 o-pairs x 2 px
#pragma unroll
        for (int q = 0; q < 8; q++) { h[q][0] = 0ull; h[q][1] = 0ull; }

        const float* fb = feats + ((long)(s * B_DIM + b) * F_DIM) * NPIX + m;
#pragma unroll 8
        for (int f = 0; f < F_DIM; f++) {
            float2 x = *(const float2*)(fb + (long)f * NPIX);
            unsigned long long x0 = pack2(x.x, x.x);
            unsigned long long x1 = pack2(x.y, x.y);
#pragma unroll
            for (int q = 0; q < 8; q++) {
                unsigned long long w = *(const unsigned long long*)&s_wT[f][wo + 2 * q];
                h[q][0] = fma2(w, x0, h[q][0]);
                h[q][1] = fma2(w, x1, h[q][1]);
            }
        }
        // p contribution (recomputed per s; L1-hot after s=0)
#pragma unroll 8
        for (int p = 0; p < P_DIM; p++) {
            float2 x = *(const float2*)(pbase + (long)p * NPIX);
            unsigned long long x0 = pack2(x.x, x.x);
            unsigned long long x1 = pack2(x.y, x.y);
#pragma unroll
            for (int q = 0; q < 8; q++) {
                unsigned long long w = *(const unsigned long long*)&s_wT[F_DIM + p][wo + 2 * q];
                h[q][0] = fma2(w, x0, h[q][0]);
                h[q][1] = fma2(w, x1, h[q][1]);
            }
        }

        // partial logits over this thread's 16 o's
        float l0 = 0.f, l1 = 0.f;
#pragma unroll
        for (int q = 0; q < 8; q++) {
            float b0 = s_bias[wo + 2 * q], b1 = s_bias[wo + 2 * q + 1];
            float w20 = s_w2[wo + 2 * q],  w21 = s_w2[wo + 2 * q + 1];
            float a, c;
            unpack2(h[q][0], a, c);
            l0 += fmaxf(a + b0, 0.f) * w20 + fmaxf(c + b1, 0.f) * w21;
            unpack2(h[q][1], a, c);
            l1 += fmaxf(a + b0, 0.f) * w20 + fmaxf(c + b1, 0.f) * w21;
        }
        // combine with partner thread (other 16 o's)
        l0 += __shfl_xor_sync(0xFFFFFFFFu, l0, 1);
        l1 += __shfl_xor_sync(0xFFFFFFFFu, l1, 1);
        logits[s][0] = l0;
        logits[s][1] = l1;
    }

    // ---- softmax over s (identical in both pair threads) ----
    float alpha[S_DIM][2];
#pragma unroll
    for (int px = 0; px < 2; px++) {
        float mx = fmaxf(fmaxf(logits[0][px], logits[1][px]),
                         fmaxf(logits[2][px], logits[3][px]));
        float sum = 0.f;
#pragma unroll
        for (int s = 0; s < S_DIM; s++) {
            float e = __expf(logits[s][px] - mx);
            alpha[s][px] = e;
            sum += e;
        }
        float inv = 1.f / sum;
#pragma unroll
        for (int s = 0; s < S_DIM; s++) alpha[s][px] *= inv;
    }

    // ---- write alpha: layout (B, S, NPIX); even pair-thread writes both px
    float* aout = out + (long)B_DIM * F_DIM * NPIX;
    if (oh == 0) {
#pragma unroll
        for (int s = 0; s < S_DIM; s++) {
            *(float2*)(aout + ((long)b * S_DIM + s) * NPIX + m) =
                make_float2(alpha[s][0], alpha[s][1]);
        }
    }

    // ---- pass 2: each pair thread takes 1 pixel, all 64 f (coalesced) ----
    const int pm = m + oh;                           // this thread's pixel
    const float al0 = alpha[0][oh], al1 = alpha[1][oh];
    const float al2 = alpha[2][oh], al3 = alpha[3][oh];
    const float* fb0 = feats + ((long)b * F_DIM) * NPIX + pm;   // s = 0
    const long   sstride = (long)B_DIM * F_DIM * NPIX;
#pragma unroll 8
    for (int f = 0; f < F_DIM; f++) {
        const float* fp = fb0 + (long)f * NPIX;
        float acc;
        acc = fp[0] * al0;
        acc = fmaf(fp[sstride],     al1, acc);
        acc = fmaf(fp[2 * sstride], al2, acc);
        acc = fmaf(fp[3 * sstride], al3, acc);
        out[((long)b * F_DIM + f) * NPIX + pm] = acc;
    }
}

// ---------------------------------------------------------------------------
// Launch: inputs in metadata order:
//   0 feats, 1 p_s, 2 w1, 3 bn_gamma, 4 bn_beta, 5 bn_mean, 6 bn_var, 7 w2, 8 b2
// d_out = [out (B*F*NPIX floats)] ++ [alpha (B*S*NPIX floats)]
// ---------------------------------------------------------------------------
extern "C" void kernel_launch(void* const* d_in, const int* in_sizes, int n_in,
                              void* d_out, int out_size) {
    const float* feats = (const float*)d_in[0];
    const float* p_s   = (const float*)d_in[1];
    const float* w1    = (const float*)d_in[2];
    const float* gam   = (const float*)d_in[3];
    const float* bet   = (const float*)d_in[4];
    const float* mean  = (const float*)d_in[5];
    const float* var   = (const float*)d_in[6];
    const float* w2    = (const float*)d_in[7];
    float* outp = (float*)d_out;

    const long total_px = (long)B_DIM * NPIX;          // 262144
    int blocks = (int)(total_px / PX_BLK);             // 1024 blocks
    gssm_kernel<<<blocks, TPB>>>(feats, p_s, w1, gam, bet, mean, var, w2, outp);
}